// round 16
// baseline (speedup 1.0000x reference)
#include <cuda_runtime.h>
#include <cstdint>
#include <math.h>

// Problem dims
#define T_SEQ 512
#define BATCH 8
#define HID   512
#define EMB   256
#define VOCAB 32000
#define M_TOT (BATCH*T_SEQ)   // 4096
#define G4H   (4*HID)         // 2048

// ---------------- scratch (device globals; no allocation allowed) -----------
__device__ float    g_x0 [M_TOT*EMB];      // gathered embeddings
__device__ float    g_xg [M_TOT*G4H];      // layer0 input-gate contributions
__device__ float    g_hs1[M_TOT*HID];      // layer1 outputs (FC input)
__device__ float    g_h0 [4][HID*BATCH];   // RING-buffered h0 (depth 4), [n][b]
__device__ float    g_h1 [2][HID*BATCH];   // double-buffered h1, [n][b]
__device__ unsigned g_bar0;                // layer0 monotonic counter
__device__ unsigned g_bar1;                // layer1 monotonic counter
__device__ unsigned g_abort;               // safety abort flag

// ---------------- embedding gather ------------------------------------------
__global__ void gather_kernel(const int* __restrict__ ids,
                              const float* __restrict__ emb) {
    int m  = blockIdx.x;
    int id = ids[m];
    const float4* s = (const float4*)(emb + (size_t)id * EMB);
    float4*       d = (float4*)(g_x0 + (size_t)m * EMB);
    d[threadIdx.x] = s[threadIdx.x];
}

// ---------------- reset: counters + the two initial-read h slots ------------
__global__ void reset_kernel() {
    int i = blockIdx.x * blockDim.x + threadIdx.x;
    if (i == 0) { g_bar0 = 0u; g_bar1 = 0u; g_abort = 0u; }
    if (i < HID * BATCH) {
        g_h0[3][i] = 0.f;     // h0_{-1} read by L0 at t=0
        g_h1[1][i] = 0.f;     // h1_{-1} read by L1 at t=0
    }
}

// ---------------- tf32 mma GEMM (static smem, known-good) -------------------
__device__ __forceinline__ float f2tf32(float x) {
    float r;
    asm("cvt.rna.tf32.f32 %0, %1;" : "=f"(r) : "f"(x));
    return r;
}

__global__ void __launch_bounds__(256)
gemm_tf32_kernel(const float* __restrict__ A, const float* __restrict__ B,
                 const float* __restrict__ bias1, const float* __restrict__ bias2,
                 float* __restrict__ C, int M, int N, int K)
{
    __shared__ float As[128][36];
    __shared__ float Bs[128][36];

    int tid  = threadIdx.x;
    int warp = tid >> 5, lane = tid & 31;
    int wm   = warp >> 2, wn = warp & 3;
    int grp  = lane >> 2, tig = lane & 3;

    int mBase = blockIdx.y << 7;
    int nBase = blockIdx.x << 7;

    float acc[4][4][4];
    #pragma unroll
    for (int a = 0; a < 4; a++)
        #pragma unroll
        for (int b = 0; b < 4; b++)
            #pragma unroll
            for (int c = 0; c < 4; c++) acc[a][b][c] = 0.f;

    for (int k0 = 0; k0 < K; k0 += 32) {
        #pragma unroll
        for (int i = 0; i < 4; i++) {
            int f  = tid + (i << 8);
            int m  = f >> 3;
            int k4 = (f & 7) << 2;
            float4 va = *(const float4*)(A + (size_t)(mBase + m) * K + k0 + k4);
            *(float4*)&As[m][k4] = make_float4(f2tf32(va.x), f2tf32(va.y),
                                               f2tf32(va.z), f2tf32(va.w));
            float4 vb = *(const float4*)(B + (size_t)(nBase + m) * K + k0 + k4);
            *(float4*)&Bs[m][k4] = make_float4(f2tf32(vb.x), f2tf32(vb.y),
                                               f2tf32(vb.z), f2tf32(vb.w));
        }
        __syncthreads();

        #pragma unroll
        for (int kk = 0; kk < 32; kk += 8) {
            uint32_t af[4][4], bf[4][2];
            #pragma unroll
            for (int mi = 0; mi < 4; mi++) {
                int r = (wm << 6) + (mi << 4);
                af[mi][0] = __float_as_uint(As[r + grp    ][kk + tig    ]);
                af[mi][1] = __float_as_uint(As[r + grp + 8][kk + tig    ]);
                af[mi][2] = __float_as_uint(As[r + grp    ][kk + tig + 4]);
                af[mi][3] = __float_as_uint(As[r + grp + 8][kk + tig + 4]);
            }
            #pragma unroll
            for (int ni = 0; ni < 4; ni++) {
                int cN = (wn << 5) + (ni << 3);
                bf[ni][0] = __float_as_uint(Bs[cN + grp][kk + tig    ]);
                bf[ni][1] = __float_as_uint(Bs[cN + grp][kk + tig + 4]);
            }
            #pragma unroll
            for (int mi = 0; mi < 4; mi++)
                #pragma unroll
                for (int ni = 0; ni < 4; ni++)
                    asm volatile(
                        "mma.sync.aligned.m16n8k8.row.col.f32.tf32.tf32.f32 "
                        "{%0,%1,%2,%3}, {%4,%5,%6,%7}, {%8,%9}, {%0,%1,%2,%3};"
                        : "+f"(acc[mi][ni][0]), "+f"(acc[mi][ni][1]),
                          "+f"(acc[mi][ni][2]), "+f"(acc[mi][ni][3])
                        : "r"(af[mi][0]), "r"(af[mi][1]),
                          "r"(af[mi][2]), "r"(af[mi][3]),
                          "r"(bf[ni][0]), "r"(bf[ni][1]));
        }
        __syncthreads();
    }

    #pragma unroll
    for (int mi = 0; mi < 4; mi++) {
        int mrow = mBase + (wm << 6) + (mi << 4) + grp;
        #pragma unroll
        for (int ni = 0; ni < 4; ni++) {
            int nc = nBase + (wn << 5) + (ni << 3) + (tig << 1);
            float b0 = bias1[nc], b1 = bias1[nc + 1];
            if (bias2) { b0 += bias2[nc]; b1 += bias2[nc + 1]; }
            float2 v0 = make_float2(acc[mi][ni][0] + b0, acc[mi][ni][1] + b1);
            float2 v1 = make_float2(acc[mi][ni][2] + b0, acc[mi][ni][3] + b1);
            *(float2*)(C + (size_t)mrow       * N + nc) = v0;
            *(float2*)(C + (size_t)(mrow + 8) * N + nc) = v1;
        }
    }
}

// ---------------- fast activations (MUFU ex2/rcp; rel err ~1e-6) ------------
__device__ __forceinline__ float fast_sig(float x) {
    float e, r;
    asm("ex2.approx.ftz.f32 %0, %1;" : "=f"(e) : "f"(-1.4426950408889634f * x));
    asm("rcp.approx.ftz.f32 %0, %1;" : "=f"(r) : "f"(1.f + e));
    return r;
}
__device__ __forceinline__ float fast_tanh(float x) {
    float e, r;
    asm("ex2.approx.ftz.f32 %0, %1;" : "=f"(e) : "f"(-2.8853900817779268f * x));
    asm("rcp.approx.ftz.f32 %0, %1;" : "=f"(r) : "f"(1.f + e));
    return 2.f * r - 1.f;
}

// ---------------- bounded acquire-poll (hang-proof) --------------------------
__device__ __forceinline__ int poll_ge(unsigned* p, unsigned target) {
    volatile unsigned* abt = (volatile unsigned*)&g_abort;
    unsigned it = 0;
    for (;;) {
        unsigned v;
        asm volatile("ld.acquire.gpu.global.u32 %0, [%1];" : "=r"(v) : "l"(p));
        if (v >= target) return 0;
        if ((++it & 63u) == 0u) {
            if (*abt) return 1;
            if (it > (1u << 22)) { atomicExch(&g_abort, 1u); return 1; }
            __nanosleep(32);
        }
    }
}

// ---------------- persistent LSTM: tensor dot, B-frags straight from L2 -----
// 128 CTAs co-resident. CTAs 0..63: layer0; 64..127: layer1; 8 units (32 gate
// rows) per CTA. No smem h buffer at all: mma B-fragments are coalesced
// __ldcg loads from the global h arrays ([n][b] layout -> lanes cover one
// 128B line). W (tf32) stays in smem for the whole sequence. Per-layer
// monotonic counters, release/acquire. h0 ring depth 4 decouples the layers.
#define NCTA_L 64
#define WST0 516
#define WST1 1036

__global__ void __launch_bounds__(256)
lstm_persist_kernel(const float* __restrict__ Whh0, const float* __restrict__ xg,
                    const float* __restrict__ Whh1, const float* __restrict__ Wih1,
                    const float* __restrict__ bi1,  const float* __restrict__ bh1,
                    float* __restrict__ hs1)
{
    extern __shared__ float sm[];
    __shared__ int s_ab;
    int tid  = threadIdx.x;
    bool isL1 = blockIdx.x >= 64;
    int cta  = isL1 ? blockIdx.x - 64 : blockIdx.x;
    int base = cta << 3;

    const int WST = isL1 ? WST1 : WST0;
    float* Ws = sm;                    // 32 rows x WST (tf32)
    float* Pt = sm + 32 * WST;         // 256 x 9 k-partials
    float* Cs = Pt + 256 * 9;          // 64 cell states

    // ---- one-time W staging (tf32) ----
    if (!isL1) {
        #pragma unroll 4
        for (int i = tid; i < 4096; i += 256) {
            int r = i >> 7, c4 = (i & 127) << 2;
            int g = r >> 3, u = r & 7;
            float4 v = *(const float4*)(Whh0 + (size_t)((g << 9) + base + u) * HID + c4);
            *(float4*)(Ws + r * WST0 + c4) =
                make_float4(f2tf32(v.x), f2tf32(v.y), f2tf32(v.z), f2tf32(v.w));
        }
    } else {
        #pragma unroll 4
        for (int i = tid; i < 8192; i += 256) {
            int r = i >> 8, c4 = (i & 255) << 2;
            int g = r >> 3, u = r & 7;
            const float* src = (c4 < 512) ? Whh1 : Wih1;
            int col = (c4 < 512) ? c4 : c4 - 512;
            float4 v = *(const float4*)(src + (size_t)((g << 9) + base + u) * HID + col);
            *(float4*)(Ws + r * WST1 + c4) =
                make_float4(f2tf32(v.x), f2tf32(v.y), f2tf32(v.z), f2tf32(v.w));
        }
    }
    if (tid < 64) Cs[tid] = 0.f;
    if (tid == 0) s_ab = 0;

    int au = tid >> 3, ab_ = tid & 7;        // act-thread coords (tid < 64)
    float bias_g[4] = {0.f, 0.f, 0.f, 0.f};
    if (isL1 && tid < 64) {
        #pragma unroll
        for (int g = 0; g < 4; g++) {
            int row = (g << 9) + base + au;
            bias_g[g] = __ldg(bi1 + row) + __ldg(bh1 + row);
        }
    }
    __syncthreads();

    // mma mapping (validated in R15): warp w = k-slice; grp = lane>>2,
    // tig = lane&3. A-frags from Ws; B-frags straight from global h.
    int w    = tid >> 5, lane = tid & 31;
    int grp  = lane >> 2, tig = lane & 3;
    int kpw  = isL1 ? 16 : 8;                // mma k-steps per warp
    int kb0  = w * kpw * 8;                  // starting K column

    for (int t = 0; t < T_SEQ; t++) {
        int ab = 0;
        if (!isL1) {
            if (t)      ab |= poll_ge(&g_bar0, 64u * (unsigned)t);
            if (t >= 4) ab |= poll_ge(&g_bar1, 64u * (unsigned)(t - 3));
        } else {
            if (t)      ab |= poll_ge(&g_bar1, 64u * (unsigned)t);
            ab |= poll_ge(&g_bar0, 64u * (unsigned)(t + 1));
        }

        // L0 act threads prefetch xg early
        float xv0 = 0.f, xv1 = 0.f, xv2 = 0.f, xv3 = 0.f;
        if (!isL1 && tid < 64) {
            const float* xr = xg + (size_t)((ab_ << 9) + t) * G4H + base + au;
            xv0 = __ldg(xr);        xv1 = __ldg(xr + 512);
            xv2 = __ldg(xr + 1024); xv3 = __ldg(xr + 1536);
        }

        // B-fragment source (per-warp uniform; h stored pre-rounded to tf32)
        const float* hsrc;
        int koff = 0;
        if (!isL1)        hsrc = g_h0[(t + 3) & 3];               // h0_{t-1}
        else if (w < 4)   hsrc = g_h1[(t + 1) & 1];               // h1_{t-1}
        else            { hsrc = g_h0[t & 3]; koff = 512; }       // h0_t

        {   // ---- tensor dot: D[32 rows x 8 batch] over this warp's k-slice ----
            float acc[2][4];
            #pragma unroll
            for (int m = 0; m < 2; m++)
                #pragma unroll
                for (int d = 0; d < 4; d++) acc[m][d] = 0.f;

            #pragma unroll 4
            for (int ks = 0; ks < kpw; ks++) {
                int kk = kb0 + (ks << 3);
                int kc = kk - koff + tig;
                uint32_t b0 = __float_as_uint(__ldcg(hsrc + (kc << 3) + grp));
                uint32_t b1 = __float_as_uint(__ldcg(hsrc + ((kc + 4) << 3) + grp));
                #pragma unroll
                for (int m = 0; m < 2; m++) {
                    int r = m << 4;
                    uint32_t a0 = __float_as_uint(Ws[(r + grp    ) * WST + kk + tig    ]);
                    uint32_t a1 = __float_as_uint(Ws[(r + grp + 8) * WST + kk + tig    ]);
                    uint32_t a2 = __float_as_uint(Ws[(r + grp    ) * WST + kk + tig + 4]);
                    uint32_t a3 = __float_as_uint(Ws[(r + grp + 8) * WST + kk + tig + 4]);
                    asm volatile(
                        "mma.sync.aligned.m16n8k8.row.col.f32.tf32.tf32.f32 "
                        "{%0,%1,%2,%3}, {%4,%5,%6,%7}, {%8,%9}, {%0,%1,%2,%3};"
                        : "+f"(acc[m][0]), "+f"(acc[m][1]),
                          "+f"(acc[m][2]), "+f"(acc[m][3])
                        : "r"(a0), "r"(a1), "r"(a2), "r"(a3),
                          "r"(b0), "r"(b1));
                }
            }
            #pragma unroll
            for (int m = 0; m < 2; m++) {
                int r0 = (m << 4) + grp;
                Pt[((r0    ) * 8 + (tig << 1)    ) * 9 + w] = acc[m][0];
                Pt[((r0    ) * 8 + (tig << 1) + 1) * 9 + w] = acc[m][1];
                Pt[((r0 + 8) * 8 + (tig << 1)    ) * 9 + w] = acc[m][2];
                Pt[((r0 + 8) * 8 + (tig << 1) + 1) * 9 + w] = acc[m][3];
            }
        }
        if (ab) s_ab = 1;
        __syncthreads();                 // sync1: Pt complete; s_ab stable
        if (s_ab) return;                // uniform, hang-proof exit

        if (tid < 64) {                  // fused reduce + act + publish
            float gs[4];
            #pragma unroll
            for (int g = 0; g < 4; g++) {
                int slot = (((g << 3) + au) << 3) + ab_;
                float s = 0.f;
                #pragma unroll
                for (int k = 0; k < 8; k++) s += Pt[slot * 9 + k];
                gs[g] = s;
            }
            if (!isL1) { gs[0] += xv0; gs[1] += xv1; gs[2] += xv2; gs[3] += xv3; }
            else       { gs[0] += bias_g[0]; gs[1] += bias_g[1];
                         gs[2] += bias_g[2]; gs[3] += bias_g[3]; }
            float i_ = fast_sig(gs[0]);
            float f_ = fast_sig(gs[1]);
            float gg = fast_tanh(gs[2]);
            float o_ = fast_sig(gs[3]);
            float c  = f_ * Cs[tid] + i_ * gg;
            Cs[tid]  = c;
            float h  = f2tf32(o_ * fast_tanh(c));   // round once at the source
            if (!isL1) {
                g_h0[t & 3][(base << 3) + tid] = h;
            } else {
                g_h1[t & 1][(base << 3) + tid] = h;
                hs1[(size_t)((ab_ << 9) + t) * HID + base + au] = h;
            }
        }
        __syncthreads();                 // sync2: h stores CTA-wide HB

        if (tid == 0)                    // release: orders prior stores
            asm volatile("red.release.gpu.global.add.u32 [%0], 1;"
                         :: "l"(isL1 ? &g_bar1 : &g_bar0) : "memory");
    }
}

// ---------------- launch -----------------------------------------------------
extern "C" void kernel_launch(void* const* d_in, const int* in_sizes, int n_in,
                              void* d_out, int out_size)
{
    (void)in_sizes; (void)n_in; (void)out_size;
    const int*   ids   = (const int*)d_in[0];
    const float* emb   = (const float*)d_in[1];
    const float* W_ih0 = (const float*)d_in[2];
    const float* W_hh0 = (const float*)d_in[3];
    const float* b_ih0 = (const float*)d_in[4];
    const float* b_hh0 = (const float*)d_in[5];
    const float* W_ih1 = (const float*)d_in[6];
    const float* W_hh1 = (const float*)d_in[7];
    const float* b_ih1 = (const float*)d_in[8];
    const float* b_hh1 = (const float*)d_in[9];
    const float* W_fc  = (const float*)d_in[10];
    const float* b_fc  = (const float*)d_in[11];
    float* out = (float*)d_out;

    float *x0, *xgp, *hs1;
    cudaGetSymbolAddress((void**)&x0,  g_x0);
    cudaGetSymbolAddress((void**)&xgp, g_xg);
    cudaGetSymbolAddress((void**)&hs1, g_hs1);

    // dynamic smem (L1 branch): 32*WST1 + 256*9 + 64 floats = 142080 B
    const int per_smem = (32 * WST1 + 256 * 9 + 64) * (int)sizeof(float);
    cudaFuncSetAttribute(lstm_persist_kernel,
                         cudaFuncAttributeMaxDynamicSharedMemorySize, per_smem);

    // 1) gather embeddings
    gather_kernel<<<M_TOT, EMB / 4>>>(ids, emb);

    // 2) xg = x0 @ W_ih0^T + b_ih0 + b_hh0     [4096 x 2048], K=256
    gemm_tf32_kernel<<<dim3(G4H / 128, M_TOT / 128), 256>>>(
        x0, W_ih0, b_ih0, b_hh0, xgp, M_TOT, G4H, EMB);

    // 3) reset counters + initial h slots
    reset_kernel<<<(HID * BATCH + 255) / 256, 256>>>();

    // 4) both LSTM layers, decoupled, in ONE persistent launch
    lstm_persist_kernel<<<2 * NCTA_L, 256, per_smem>>>(
        W_hh0, xgp, W_hh1, W_ih1, b_ih1, b_hh1, hs1);

    // 5) logits = hs1 @ W_fc^T + b_fc          [4096 x 32000], K=512
    gemm_tf32_kernel<<<dim3(VOCAB / 128, M_TOT / 128), 256>>>(
        hs1, W_fc, b_fc, nullptr, out, M_TOT, VOCAB, HID);
}

// round 17
// speedup vs baseline: 1.1093x; 1.1093x over previous
#include <cuda_runtime.h>
#include <cstdint>
#include <math.h>

// Problem dims
#define T_SEQ 512
#define BATCH 8
#define HID   512
#define EMB   256
#define VOCAB 32000
#define M_TOT (BATCH*T_SEQ)   // 4096
#define G4H   (4*HID)         // 2048
#define NTILE ((M_TOT/128)*(VOCAB/128))   // 8000 FC tiles

// ---------------- scratch (device globals; no allocation allowed) -----------
__device__ float    g_x0 [M_TOT*EMB];      // gathered embeddings
__device__ float    g_xg [M_TOT*G4H];      // layer0 input-gate contributions
__device__ float    g_hs1[M_TOT*HID];      // layer1 outputs (FC input)
__device__ float    g_h0 [4][HID*BATCH];   // RING-buffered h0 (depth 4), [n][b]
__device__ float    g_h1 [2][HID*BATCH];   // double-buffered h1, [n][b]
__device__ unsigned g_bar0;                // layer0 monotonic counter
__device__ unsigned g_bar1;                // layer1 monotonic counter
__device__ unsigned g_fcwork;              // FC tile work-steal counter
__device__ unsigned g_abort;               // safety abort flag

// ---------------- embedding gather ------------------------------------------
__global__ void gather_kernel(const int* __restrict__ ids,
                              const float* __restrict__ emb) {
    int m  = blockIdx.x;
    int id = ids[m];
    const float4* s = (const float4*)(emb + (size_t)id * EMB);
    float4*       d = (float4*)(g_x0 + (size_t)m * EMB);
    d[threadIdx.x] = s[threadIdx.x];
}

// ---------------- reset: counters + the two initial-read h slots ------------
__global__ void reset_kernel() {
    int i = blockIdx.x * blockDim.x + threadIdx.x;
    if (i == 0) { g_bar0 = 0u; g_bar1 = 0u; g_fcwork = 0u; g_abort = 0u; }
    if (i < HID * BATCH) {
        g_h0[3][i] = 0.f;     // h0_{-1} read by L0 at t=0
        g_h1[1][i] = 0.f;     // h1_{-1} read by L1 at t=0
    }
}

// ---------------- tf32 helpers ----------------------------------------------
__device__ __forceinline__ float f2tf32(float x) {
    float r;
    asm("cvt.rna.tf32.f32 %0, %1;" : "=f"(r) : "f"(x));
    return r;
}

// ---------------- standalone tf32 mma GEMM (xg pre-GEMM only) ---------------
__global__ void __launch_bounds__(256)
gemm_tf32_kernel(const float* __restrict__ A, const float* __restrict__ B,
                 const float* __restrict__ bias1, const float* __restrict__ bias2,
                 float* __restrict__ C, int M, int N, int K)
{
    __shared__ float As[128][36];
    __shared__ float Bs[128][36];

    int tid  = threadIdx.x;
    int warp = tid >> 5, lane = tid & 31;
    int wm   = warp >> 2, wn = warp & 3;
    int grp  = lane >> 2, tig = lane & 3;

    int mBase = blockIdx.y << 7;
    int nBase = blockIdx.x << 7;

    float acc[4][4][4];
    #pragma unroll
    for (int a = 0; a < 4; a++)
        #pragma unroll
        for (int b = 0; b < 4; b++)
            #pragma unroll
            for (int c = 0; c < 4; c++) acc[a][b][c] = 0.f;

    for (int k0 = 0; k0 < K; k0 += 32) {
        #pragma unroll
        for (int i = 0; i < 4; i++) {
            int f  = tid + (i << 8);
            int m  = f >> 3;
            int k4 = (f & 7) << 2;
            float4 va = *(const float4*)(A + (size_t)(mBase + m) * K + k0 + k4);
            *(float4*)&As[m][k4] = make_float4(f2tf32(va.x), f2tf32(va.y),
                                               f2tf32(va.z), f2tf32(va.w));
            float4 vb = *(const float4*)(B + (size_t)(nBase + m) * K + k0 + k4);
            *(float4*)&Bs[m][k4] = make_float4(f2tf32(vb.x), f2tf32(vb.y),
                                               f2tf32(vb.z), f2tf32(vb.w));
        }
        __syncthreads();

        #pragma unroll
        for (int kk = 0; kk < 32; kk += 8) {
            uint32_t af[4][4], bf[4][2];
            #pragma unroll
            for (int mi = 0; mi < 4; mi++) {
                int r = (wm << 6) + (mi << 4);
                af[mi][0] = __float_as_uint(As[r + grp    ][kk + tig    ]);
                af[mi][1] = __float_as_uint(As[r + grp + 8][kk + tig    ]);
                af[mi][2] = __float_as_uint(As[r + grp    ][kk + tig + 4]);
                af[mi][3] = __float_as_uint(As[r + grp + 8][kk + tig + 4]);
            }
            #pragma unroll
            for (int ni = 0; ni < 4; ni++) {
                int cN = (wn << 5) + (ni << 3);
                bf[ni][0] = __float_as_uint(Bs[cN + grp][kk + tig    ]);
                bf[ni][1] = __float_as_uint(Bs[cN + grp][kk + tig + 4]);
            }
            #pragma unroll
            for (int mi = 0; mi < 4; mi++)
                #pragma unroll
                for (int ni = 0; ni < 4; ni++)
                    asm volatile(
                        "mma.sync.aligned.m16n8k8.row.col.f32.tf32.tf32.f32 "
                        "{%0,%1,%2,%3}, {%4,%5,%6,%7}, {%8,%9}, {%0,%1,%2,%3};"
                        : "+f"(acc[mi][ni][0]), "+f"(acc[mi][ni][1]),
                          "+f"(acc[mi][ni][2]), "+f"(acc[mi][ni][3])
                        : "r"(af[mi][0]), "r"(af[mi][1]),
                          "r"(af[mi][2]), "r"(af[mi][3]),
                          "r"(bf[ni][0]), "r"(bf[ni][1]));
        }
        __syncthreads();
    }

    #pragma unroll
    for (int mi = 0; mi < 4; mi++) {
        int mrow = mBase + (wm << 6) + (mi << 4) + grp;
        #pragma unroll
        for (int ni = 0; ni < 4; ni++) {
            int nc = nBase + (wn << 5) + (ni << 3) + (tig << 1);
            float b0 = bias1[nc], b1 = bias1[nc + 1];
            if (bias2) { b0 += bias2[nc]; b1 += bias2[nc + 1]; }
            float2 v0 = make_float2(acc[mi][ni][0] + b0, acc[mi][ni][1] + b1);
            float2 v1 = make_float2(acc[mi][ni][2] + b0, acc[mi][ni][3] + b1);
            *(float2*)(C + (size_t)mrow       * N + nc) = v0;
            *(float2*)(C + (size_t)(mrow + 8) * N + nc) = v1;
        }
    }
}

// ---------------- fast activations (MUFU ex2/rcp; rel err ~1e-6) ------------
__device__ __forceinline__ float fast_sig(float x) {
    float e, r;
    asm("ex2.approx.ftz.f32 %0, %1;" : "=f"(e) : "f"(-1.4426950408889634f * x));
    asm("rcp.approx.ftz.f32 %0, %1;" : "=f"(r) : "f"(1.f + e));
    return r;
}
__device__ __forceinline__ float fast_tanh(float x) {
    float e, r;
    asm("ex2.approx.ftz.f32 %0, %1;" : "=f"(e) : "f"(-2.8853900817779268f * x));
    asm("rcp.approx.ftz.f32 %0, %1;" : "=f"(r) : "f"(1.f + e));
    return 2.f * r - 1.f;
}

// ---------------- bounded acquire-poll (hang-proof) --------------------------
__device__ __forceinline__ int poll_ge(unsigned* p, unsigned target) {
    volatile unsigned* abt = (volatile unsigned*)&g_abort;
    unsigned it = 0;
    for (;;) {
        unsigned v;
        asm volatile("ld.acquire.gpu.global.u32 %0, [%1];" : "=r"(v) : "l"(p));
        if (v >= target) return 0;
        if ((++it & 63u) == 0u) {
            if (*abt) return 1;
            if (it > (1u << 22)) { atomicExch(&g_abort, 1u); return 1; }
            __nanosleep(32);
        }
    }
}

// ---------------- fused persistent kernel ------------------------------------
// 148 CTAs: 0..63 layer0, 64..127 layer1 (R16 recurrence, unchanged logic),
// 128..147 immediately work-steal FC tiles; recurrence CTAs join the FC pool
// after their 512 steps. FC tile j: tb=j/2000, b=(j%2000)/250, n=j%250;
// gated on bar1 >= 8192*(tb+1) (hs1 rows t < 128*(tb+1) all published).
#define NCTA_L 64
#define WST0 516
#define WST1 1036

__global__ void __launch_bounds__(256)
fused_kernel(const float* __restrict__ Whh0, const float* __restrict__ xg,
             const float* __restrict__ Whh1, const float* __restrict__ Wih1,
             const float* __restrict__ bi1,  const float* __restrict__ bh1,
             const float* __restrict__ Wfc,  const float* __restrict__ bfc,
             float* __restrict__ hs1,        float* __restrict__ out)
{
    extern __shared__ float sm[];
    __shared__ int s_ab, s_job, s_flag;
    int tid = threadIdx.x;

    if (blockIdx.x < 128) {
        // ================== RECURRENCE (R16, unchanged) ==================
        bool isL1 = blockIdx.x >= 64;
        int cta  = isL1 ? blockIdx.x - 64 : blockIdx.x;
        int base = cta << 3;

        const int WST = isL1 ? WST1 : WST0;
        float* Ws = sm;                    // 32 rows x WST (tf32)
        float* Pt = sm + 32 * WST;         // 256 x 9 k-partials
        float* Cs = Pt + 256 * 9;          // 64 cell states

        if (!isL1) {
            #pragma unroll 4
            for (int i = tid; i < 4096; i += 256) {
                int r = i >> 7, c4 = (i & 127) << 2;
                int g = r >> 3, u = r & 7;
                float4 v = *(const float4*)(Whh0 + (size_t)((g << 9) + base + u) * HID + c4);
                *(float4*)(Ws + r * WST0 + c4) =
                    make_float4(f2tf32(v.x), f2tf32(v.y), f2tf32(v.z), f2tf32(v.w));
            }
        } else {
            #pragma unroll 4
            for (int i = tid; i < 8192; i += 256) {
                int r = i >> 8, c4 = (i & 255) << 2;
                int g = r >> 3, u = r & 7;
                const float* src = (c4 < 512) ? Whh1 : Wih1;
                int col = (c4 < 512) ? c4 : c4 - 512;
                float4 v = *(const float4*)(src + (size_t)((g << 9) + base + u) * HID + col);
                *(float4*)(Ws + r * WST1 + c4) =
                    make_float4(f2tf32(v.x), f2tf32(v.y), f2tf32(v.z), f2tf32(v.w));
            }
        }
        if (tid < 64) Cs[tid] = 0.f;
        if (tid == 0) s_ab = 0;

        int au = tid >> 3, ab_ = tid & 7;
        float bias_g[4] = {0.f, 0.f, 0.f, 0.f};
        if (isL1 && tid < 64) {
            #pragma unroll
            for (int g = 0; g < 4; g++) {
                int row = (g << 9) + base + au;
                bias_g[g] = __ldg(bi1 + row) + __ldg(bh1 + row);
            }
        }
        __syncthreads();

        int w    = tid >> 5, lane = tid & 31;
        int grp  = lane >> 2, tig = lane & 3;
        int kpw  = isL1 ? 16 : 8;
        int kb0  = w * kpw * 8;

        for (int t = 0; t < T_SEQ; t++) {
            int ab = 0;
            if (!isL1) {
                if (t)      ab |= poll_ge(&g_bar0, 64u * (unsigned)t);
                if (t >= 4) ab |= poll_ge(&g_bar1, 64u * (unsigned)(t - 3));
            } else {
                if (t)      ab |= poll_ge(&g_bar1, 64u * (unsigned)t);
                ab |= poll_ge(&g_bar0, 64u * (unsigned)(t + 1));
            }

            float xv0 = 0.f, xv1 = 0.f, xv2 = 0.f, xv3 = 0.f;
            if (!isL1 && tid < 64) {
                const float* xr = xg + (size_t)((ab_ << 9) + t) * G4H + base + au;
                xv0 = __ldg(xr);        xv1 = __ldg(xr + 512);
                xv2 = __ldg(xr + 1024); xv3 = __ldg(xr + 1536);
            }

            const float* hsrc;
            int koff = 0;
            if (!isL1)        hsrc = g_h0[(t + 3) & 3];
            else if (w < 4)   hsrc = g_h1[(t + 1) & 1];
            else            { hsrc = g_h0[t & 3]; koff = 512; }

            {
                float acc[2][4];
                #pragma unroll
                for (int m = 0; m < 2; m++)
                    #pragma unroll
                    for (int d = 0; d < 4; d++) acc[m][d] = 0.f;

                #pragma unroll 4
                for (int ks = 0; ks < kpw; ks++) {
                    int kk = kb0 + (ks << 3);
                    int kc = kk - koff + tig;
                    uint32_t b0 = __float_as_uint(__ldcg(hsrc + (kc << 3) + grp));
                    uint32_t b1 = __float_as_uint(__ldcg(hsrc + ((kc + 4) << 3) + grp));
                    #pragma unroll
                    for (int m = 0; m < 2; m++) {
                        int r = m << 4;
                        uint32_t a0 = __float_as_uint(Ws[(r + grp    ) * WST + kk + tig    ]);
                        uint32_t a1 = __float_as_uint(Ws[(r + grp + 8) * WST + kk + tig    ]);
                        uint32_t a2 = __float_as_uint(Ws[(r + grp    ) * WST + kk + tig + 4]);
                        uint32_t a3 = __float_as_uint(Ws[(r + grp + 8) * WST + kk + tig + 4]);
                        asm volatile(
                            "mma.sync.aligned.m16n8k8.row.col.f32.tf32.tf32.f32 "
                            "{%0,%1,%2,%3}, {%4,%5,%6,%7}, {%8,%9}, {%0,%1,%2,%3};"
                            : "+f"(acc[m][0]), "+f"(acc[m][1]),
                              "+f"(acc[m][2]), "+f"(acc[m][3])
                            : "r"(a0), "r"(a1), "r"(a2), "r"(a3),
                              "r"(b0), "r"(b1));
                    }
                }
                #pragma unroll
                for (int m = 0; m < 2; m++) {
                    int r0 = (m << 4) + grp;
                    Pt[((r0    ) * 8 + (tig << 1)    ) * 9 + w] = acc[m][0];
                    Pt[((r0    ) * 8 + (tig << 1) + 1) * 9 + w] = acc[m][1];
                    Pt[((r0 + 8) * 8 + (tig << 1)    ) * 9 + w] = acc[m][2];
                    Pt[((r0 + 8) * 8 + (tig << 1) + 1) * 9 + w] = acc[m][3];
                }
            }
            if (ab) s_ab = 1;
            __syncthreads();                 // sync1
            if (s_ab) return;                // abort: bounded exit, skip FC

            if (tid < 64) {
                float gs[4];
                #pragma unroll
                for (int g = 0; g < 4; g++) {
                    int slot = (((g << 3) + au) << 3) + ab_;
                    float s = 0.f;
                    #pragma unroll
                    for (int k = 0; k < 8; k++) s += Pt[slot * 9 + k];
                    gs[g] = s;
                }
                if (!isL1) { gs[0] += xv0; gs[1] += xv1; gs[2] += xv2; gs[3] += xv3; }
                else       { gs[0] += bias_g[0]; gs[1] += bias_g[1];
                             gs[2] += bias_g[2]; gs[3] += bias_g[3]; }
                float i_ = fast_sig(gs[0]);
                float f_ = fast_sig(gs[1]);
                float gg = fast_tanh(gs[2]);
                float o_ = fast_sig(gs[3]);
                float c  = f_ * Cs[tid] + i_ * gg;
                Cs[tid]  = c;
                float h  = f2tf32(o_ * fast_tanh(c));
                if (!isL1) {
                    g_h0[t & 3][(base << 3) + tid] = h;
                } else {
                    g_h1[t & 1][(base << 3) + tid] = h;
                    hs1[(size_t)((ab_ << 9) + t) * HID + base + au] = h;
                }
            }
            __syncthreads();                 // sync2

            if (tid == 0)
                asm volatile("red.release.gpu.global.add.u32 [%0], 1;"
                             :: "l"(isL1 ? &g_bar1 : &g_bar0) : "memory");
        }
        __syncthreads();   // recurrence done; smem reused by FC below
    }

    // ================== FC GEMM work-steal pool ==================
    // out[m][v] = hs1[m][:] . Wfc[v][:] + bfc[v];   tiles 128x128, K=512
    {
        float* As = sm;            // 128 x 36
        float* Bs = sm + 128 * 36; // 128 x 36

        int warp = tid >> 5, lane = tid & 31;
        int wm   = warp >> 2, wn = warp & 3;
        int grp  = lane >> 2, tig = lane & 3;

        int srow[4], sk4[4];
        #pragma unroll
        for (int i = 0; i < 4; i++) {
            int f = tid + (i << 8);
            srow[i] = f >> 3;
            sk4[i]  = (f & 7) << 2;
        }

        for (;;) {
            if (tid == 0) s_job = (int)atomicAdd(&g_fcwork, 1u);
            __syncthreads();
            int j = s_job;
            if (j >= NTILE) break;

            int tb = j / 2000;
            int rem = j - tb * 2000;
            int b  = rem / 250;
            int n  = rem - b * 250;

            if (tid == 0)
                s_flag = poll_ge(&g_bar1, 8192u * (unsigned)(tb + 1));
            __syncthreads();
            if (s_flag) return;          // abort path: bounded exit

            int mBase = (b << 9) + (tb << 7);
            int nBase = n << 7;

            float acc[4][4][4];
            #pragma unroll
            for (int a = 0; a < 4; a++)
                #pragma unroll
                for (int bb = 0; bb < 4; bb++)
                    #pragma unroll
                    for (int c = 0; c < 4; c++) acc[a][bb][c] = 0.f;

            for (int k0 = 0; k0 < HID; k0 += 32) {
                #pragma unroll
                for (int i = 0; i < 4; i++) {
                    float4 va = __ldcg((const float4*)(hs1 +
                                 (size_t)(mBase + srow[i]) * HID + k0 + sk4[i]));
                    *(float4*)(As + srow[i] * 36 + sk4[i]) =
                        make_float4(f2tf32(va.x), f2tf32(va.y),
                                    f2tf32(va.z), f2tf32(va.w));
                    float4 vb = *(const float4*)(Wfc +
                                 (size_t)(nBase + srow[i]) * HID + k0 + sk4[i]);
                    *(float4*)(Bs + srow[i] * 36 + sk4[i]) =
                        make_float4(f2tf32(vb.x), f2tf32(vb.y),
                                    f2tf32(vb.z), f2tf32(vb.w));
                }
                __syncthreads();

                #pragma unroll
                for (int kk = 0; kk < 32; kk += 8) {
                    uint32_t af[4][4], bf[4][2];
                    #pragma unroll
                    for (int mi = 0; mi < 4; mi++) {
                        int r = (wm << 6) + (mi << 4);
                        af[mi][0] = __float_as_uint(As[(r + grp    ) * 36 + kk + tig    ]);
                        af[mi][1] = __float_as_uint(As[(r + grp + 8) * 36 + kk + tig    ]);
                        af[mi][2] = __float_as_uint(As[(r + grp    ) * 36 + kk + tig + 4]);
                        af[mi][3] = __float_as_uint(As[(r + grp + 8) * 36 + kk + tig + 4]);
                    }
                    #pragma unroll
                    for (int ni = 0; ni < 4; ni++) {
                        int cN = (wn << 5) + (ni << 3);
                        bf[ni][0] = __float_as_uint(Bs[(cN + grp) * 36 + kk + tig    ]);
                        bf[ni][1] = __float_as_uint(Bs[(cN + grp) * 36 + kk + tig + 4]);
                    }
                    #pragma unroll
                    for (int mi = 0; mi < 4; mi++)
                        #pragma unroll
                        for (int ni = 0; ni < 4; ni++)
                            asm volatile(
                                "mma.sync.aligned.m16n8k8.row.col.f32.tf32.tf32.f32 "
                                "{%0,%1,%2,%3}, {%4,%5,%6,%7}, {%8,%9}, {%0,%1,%2,%3};"
                                : "+f"(acc[mi][ni][0]), "+f"(acc[mi][ni][1]),
                                  "+f"(acc[mi][ni][2]), "+f"(acc[mi][ni][3])
                                : "r"(af[mi][0]), "r"(af[mi][1]),
                                  "r"(af[mi][2]), "r"(af[mi][3]),
                                  "r"(bf[ni][0]), "r"(bf[ni][1]));
                }
                __syncthreads();
            }

            #pragma unroll
            for (int mi = 0; mi < 4; mi++) {
                int mrow = mBase + (wm << 6) + (mi << 4) + grp;
                #pragma unroll
                for (int ni = 0; ni < 4; ni++) {
                    int nc = nBase + (wn << 5) + (ni << 3) + (tig << 1);
                    float b0 = __ldg(bfc + nc), b1 = __ldg(bfc + nc + 1);
                    float2 v0 = make_float2(acc[mi][ni][0] + b0, acc[mi][ni][1] + b1);
                    float2 v1 = make_float2(acc[mi][ni][2] + b0, acc[mi][ni][3] + b1);
                    *(float2*)(out + (size_t)mrow       * VOCAB + nc) = v0;
                    *(float2*)(out + (size_t)(mrow + 8) * VOCAB + nc) = v1;
                }
            }
        }
    }
}

// ---------------- launch -----------------------------------------------------
extern "C" void kernel_launch(void* const* d_in, const int* in_sizes, int n_in,
                              void* d_out, int out_size)
{
    (void)in_sizes; (void)n_in; (void)out_size;
    const int*   ids   = (const int*)d_in[0];
    const float* emb   = (const float*)d_in[1];
    const float* W_ih0 = (const float*)d_in[2];
    const float* W_hh0 = (const float*)d_in[3];
    const float* b_ih0 = (const float*)d_in[4];
    const float* b_hh0 = (const float*)d_in[5];
    const float* W_ih1 = (const float*)d_in[6];
    const float* W_hh1 = (const float*)d_in[7];
    const float* b_ih1 = (const float*)d_in[8];
    const float* b_hh1 = (const float*)d_in[9];
    const float* W_fc  = (const float*)d_in[10];
    const float* b_fc  = (const float*)d_in[11];
    float* out = (float*)d_out;

    float *x0, *xgp, *hs1;
    cudaGetSymbolAddress((void**)&x0,  g_x0);
    cudaGetSymbolAddress((void**)&xgp, g_xg);
    cudaGetSymbolAddress((void**)&hs1, g_hs1);

    // dynamic smem (recurrence L1 branch dominates): 32*WST1 + 256*9 + 64 fl
    const int per_smem = (32 * WST1 + 256 * 9 + 64) * (int)sizeof(float); // 142080
    cudaFuncSetAttribute(fused_kernel,
                         cudaFuncAttributeMaxDynamicSharedMemorySize, per_smem);

    // 1) gather embeddings
    gather_kernel<<<M_TOT, EMB / 4>>>(ids, emb);

    // 2) xg = x0 @ W_ih0^T + b_ih0 + b_hh0     [4096 x 2048], K=256
    gemm_tf32_kernel<<<dim3(G4H / 128, M_TOT / 128), 256>>>(
        x0, W_ih0, b_ih0, b_hh0, xgp, M_TOT, G4H, EMB);

    // 3) reset counters + initial h slots
    reset_kernel<<<(HID * BATCH + 255) / 256, 256>>>();

    // 4) recurrence + overlapped FC, ONE persistent launch on all 148 SMs
    fused_kernel<<<148, 256, per_smem>>>(
        W_hh0, xgp, W_hh1, W_ih1, b_ih1, b_hh1, W_fc, b_fc, hs1, out);
}